// round 13
// baseline (speedup 1.0000x reference)
#include <cuda_runtime.h>
#include <cstdint>

// Unpool (max_unpool_with_argmax inverse), SMEM-staged + bulk-store epilogue:
// each block owns half an output row (64 w2 x 128 ch = 32KB contiguous),
// computes the 2x2-window select into SMEM, then writes it with ONE
// cp.async.bulk shared->global (async-proxy DMA, bypassing the per-thread
// SM store path that all prior variants plateaued on).
// out[o] = (mask == o) ? val : 0. Mask is int32 (JAX x64 off).
//
// Shapes: val (16,64,64,128) f32, mask same int32, out (16,128,128,128) f32.

namespace {
constexpr int THREADS = 256;
constexpr int CHUNK_BYTES = 64 * 128 * 4;   // 32 KB per block
}

__global__ __launch_bounds__(THREADS) void unpool_bulk_kernel(
    const float4* __restrict__ val4,
    const int4*   __restrict__ mask4,
    float*        __restrict__ out)
{
    __shared__ __align__(128) float4 s_out[2048];   // 32 KB

    const int bid  = blockIdx.x;        // 0..4095
    const int half = bid & 1;           // which half of the output row (w2)
    const int h2   = (bid >> 1) & 127;
    const int b    = bid >> 8;
    const int h    = h2 >> 1;
    const int dh   = h2 & 1;
    (void)dh;

    // Input slab: row (b,h), w in [half*32, half*32+32) -> 1024 float4 chunks.
    const int in_base4 = (((b << 6) + h) << 11) + (half << 10);
    // Output row base (elements) and this block's contiguous 8192-elem chunk.
    const int row_base = ((b << 7) + h2) << 14;
    float* const dst   = out + row_base + (half << 13);

    // Batch all 8 loads (4 val + 4 mask) for MLP.
    float4 v[4];
    int4   m[4];
    #pragma unroll
    for (int k = 0; k < 4; ++k) {
        const int idx = threadIdx.x + (k << 8);
        v[k] = __ldg(&val4 [in_base4 + idx]);
        m[k] = __ldg(&mask4[in_base4 + idx]);
    }

    #pragma unroll
    for (int k = 0; k < 4; ++k) {
        const int idx   = threadIdx.x + (k << 8);   // float4 index in slab
        const int w_rel = idx >> 5;                 // 0..31
        const int c4    = idx & 31;                 // float4 index in channel
        const int c     = c4 << 2;

        #pragma unroll
        for (int dw = 0; dw < 2; ++dw) {
            const int w2_rel = (w_rel << 1) + dw;   // 0..63
            const int o = row_base + (((half << 6) + w2_rel) << 7) + c;
            float4 r;
            r.x = (m[k].x == o    ) ? v[k].x : 0.0f;
            r.y = (m[k].y == o + 1) ? v[k].y : 0.0f;
            r.z = (m[k].z == o + 2) ? v[k].z : 0.0f;
            r.w = (m[k].w == o + 3) ? v[k].w : 0.0f;
            s_out[(w2_rel << 5) + c4] = r;          // conflict-free STS
        }
    }

    __syncthreads();

    if (threadIdx.x == 0) {
        uint32_t s_addr;
        asm("{ .reg .u64 t; cvta.to.shared.u64 t, %1; cvt.u32.u64 %0, t; }"
            : "=r"(s_addr) : "l"(s_out));
        asm volatile("fence.proxy.async.shared::cta;" ::: "memory");
        asm volatile(
            "cp.async.bulk.global.shared::cta.bulk_group [%0], [%1], %2;"
            :: "l"(dst), "r"(s_addr), "r"(CHUNK_BYTES) : "memory");
        asm volatile("cp.async.bulk.commit_group;" ::: "memory");
        asm volatile("cp.async.bulk.wait_group 0;" ::: "memory");
    }
    __syncthreads();   // block may not exit (SMEM realloc) before DMA completes
}

extern "C" void kernel_launch(void* const* d_in, const int* in_sizes, int n_in,
                              void* d_out, int out_size)
{
    const float4* val4  = (const float4*)d_in[0];
    const int4*   mask4 = (const int4*)d_in[1];
    float*        out   = (float*)d_out;

    const int blocks = 16 * 128 * 2;   // b * h2 * half = 4096

    unpool_bulk_kernel<<<blocks, THREADS>>>(val4, mask4, out);
}

// round 14
// speedup vs baseline: 1.0009x; 1.0009x over previous
#include <cuda_runtime.h>
#include <cstdint>

// Unpool (max_unpool_with_argmax inverse), input-centric, ILP=2 with a hard
// 32-register cap so occupancy stays at the R4 level (R7's ILP=4 regression
// was an occupancy artifact: regs 40 -> occ 59%). Each thread loads two
// val/mask float4 chunks up front (MLP=4), then issues 8 independent
// streaming stores. out[o] = (mask == o) ? val : 0. Mask is int32.
//
// Shapes: val (16,64,64,128) f32, mask same int32, out (16,128,128,128) f32.

namespace {
constexpr int IN_VEC  = (16 * 64 * 64 * 128) / 4;  // 2,097,152 float4 chunks
constexpr int THREADS = 256;
constexpr int ILP     = 2;
}

__global__ __launch_bounds__(THREADS, 8)   // force <=32 regs -> full occupancy
void unpool_scatter4_ilp2_kernel(
    const float4* __restrict__ val4,
    const int4*   __restrict__ mask4,
    float4*       __restrict__ out4)
{
    const int t0 = blockIdx.x * (THREADS * ILP) + threadIdx.x;

    // Batch the 4 loads first: 4 outstanding 16B requests per thread.
    float4 v0 = __ldg(&val4 [t0]);
    int4   m0 = __ldg(&mask4[t0]);
    float4 v1 = __ldg(&val4 [t0 + THREADS]);
    int4   m1 = __ldg(&mask4[t0 + THREADS]);

    #pragma unroll
    for (int j = 0; j < ILP; ++j) {
        const int t = t0 + j * THREADS;
        const int i = t << 2;               // flat input element index

        const int c = i & 127;
        const int w = (i >> 7)  & 63;
        const int h = (i >> 13) & 63;
        const int b = i >> 19;

        const float4 v = (j == 0) ? v0 : v1;
        const int4   m = (j == 0) ? m0 : m1;

        // Output flat base: (b<<21) + (2h<<14) + (2w<<7) + c
        const int base = (b << 21) + (h << 15) + (w << 8) + c;

        #pragma unroll
        for (int dh = 0; dh < 2; ++dh) {
            #pragma unroll
            for (int dw = 0; dw < 2; ++dw) {
                const int o = base + (dh << 14) + (dw << 7);
                float4 r;
                r.x = (m.x == o    ) ? v.x : 0.0f;
                r.y = (m.y == o + 1) ? v.y : 0.0f;
                r.z = (m.z == o + 2) ? v.z : 0.0f;
                r.w = (m.w == o + 3) ? v.w : 0.0f;
                __stcs(&out4[o >> 2], r);   // streaming store
            }
        }
    }
}

extern "C" void kernel_launch(void* const* d_in, const int* in_sizes, int n_in,
                              void* d_out, int out_size)
{
    const float4* val4  = (const float4*)d_in[0];
    const int4*   mask4 = (const int4*)d_in[1];
    float4*       out4  = (float4*)d_out;

    const int blocks = IN_VEC / (THREADS * ILP);   // 4096

    unpool_scatter4_ilp2_kernel<<<blocks, THREADS>>>(val4, mask4, out4);
}

// round 17
// speedup vs baseline: 1.0463x; 1.0454x over previous
#include <cuda_runtime.h>
#include <cstdint>

// FINAL: Unpool (max_unpool_with_argmax inverse), input-centric scatter.
// One thread loads one val float4 + mask int4 at input (b,h,w,c..c+3) and
// emits the four 2x2-window output float4s with streaming stores.
// out[o] = (mask == o) ? val : 0. Mask is int32 (JAX x64 disabled).
//
// Converged result of the optimization campaign: seven structural variants
// (gather, scatter x {.cs,.wt,policy-hint}, ILP 2/4, SMEM+cp.async.bulk)
// all plateau at ~29.5us / DRAM~60% -- the binder is the L2->DRAM write
// drain (~4.9 TB/s effective for this write-dominated stream), and the
// 134MB output write is irreducible. This variant had the best kernel time
// (29.44us, ~7% above the write-drain floor). Verified passing at R4.
//
// Shapes: val (16,64,64,128) f32, mask same int32, out (16,128,128,128) f32.

namespace {
constexpr int C  = 128;
constexpr int IN_ELEMS = 16 * 64 * 64 * 128;   // 8,388,608
}

__global__ __launch_bounds__(256) void unpool_scatter4_kernel(
    const float4* __restrict__ val4,
    const int4*   __restrict__ mask4,
    float4*       __restrict__ out4)
{
    const int t = blockIdx.x * blockDim.x + threadIdx.x;   // < 2^21
    const int i = t << 2;                                  // flat input elem idx

    const int c = i & (C - 1);
    const int w = (i >> 7)  & 63;
    const int h = (i >> 13) & 63;
    const int b = i >> 19;

    const float4 v = __ldg(&val4[t]);
    const int4   m = __ldg(&mask4[t]);

    // Output flat base: (b<<21) + (2h<<14) + (2w<<7) + c
    const int base = (b << 21) + (h << 15) + (w << 8) + c;

    #pragma unroll
    for (int dh = 0; dh < 2; ++dh) {
        #pragma unroll
        for (int dw = 0; dw < 2; ++dw) {
            const int o = base + (dh << 14) + (dw << 7);
            float4 r;
            r.x = (m.x == o    ) ? v.x : 0.0f;
            r.y = (m.y == o + 1) ? v.y : 0.0f;
            r.z = (m.z == o + 2) ? v.z : 0.0f;
            r.w = (m.w == o + 3) ? v.w : 0.0f;
            __stcs(&out4[o >> 2], r);    // streaming: keep inputs L2-resident
        }
    }
}

extern "C" void kernel_launch(void* const* d_in, const int* in_sizes, int n_in,
                              void* d_out, int out_size)
{
    const float4* val4  = (const float4*)d_in[0];
    const int4*   mask4 = (const int4*)d_in[1];
    float4*       out4  = (float4*)d_out;

    const int n_vec   = IN_ELEMS >> 2;       // 2,097,152 threads
    const int threads = 256;
    const int blocks  = n_vec / threads;     // 8192

    unpool_scatter4_kernel<<<blocks, threads>>>(val4, mask4, out4);
}